// round 13
// baseline (speedup 1.0000x reference)
#include <cuda_runtime.h>
#include <cstdint>

// logits [16, 2048, 1] fp32, seq_len [16] i32, out [16, 2048, 2048] fp32.
#define BB 16
#define TT 2048
#define WPB 8                 // warps per block; one output row per warp
#define THREADS (WPB * 32)

// 256-bit store (st.global.cs.v8.b32, sm_100+): 32B per thread per store,
// 1KB contiguous per warp-instruction. ptr must be 32B-aligned.
__device__ __forceinline__ void stcs_v8(float* ptr, const float* v) {
    asm volatile(
        "st.global.cs.v8.b32 [%0], {%1, %2, %3, %4, %5, %6, %7, %8};"
        :: "l"(ptr),
           "r"(__float_as_uint(v[0])), "r"(__float_as_uint(v[1])),
           "r"(__float_as_uint(v[2])), "r"(__float_as_uint(v[3])),
           "r"(__float_as_uint(v[4])), "r"(__float_as_uint(v[5])),
           "r"(__float_as_uint(v[6])), "r"(__float_as_uint(v[7]))
        : "memory");
}

// R7 structure (write-wall kernel, ~42us) with 256-bit stores: each thread
// owns 8 CONTIGUOUS floats per chunk (32B-aligned), halving store
// instruction count and doubling burst size on the pure write stream.
//
// Max-free softmax is exact: rel values in (0.0067, 0.9933) -> exp in (1, e),
// no overflow; masked entries exactly 0, matching the reference's fp32
// exp(-1e9 - max) == 0.
__global__ __launch_bounds__(THREADS, 3) void fused_kernel(
    const float* __restrict__ logits,
    const int* __restrict__ seq_len,
    float* __restrict__ out)
{
    __shared__ float s_scores[TT];

    const int b    = blockIdx.y;
    const int tid  = threadIdx.x;
    const int warp = tid >> 5;
    const int lane = tid & 31;
    const int L    = seq_len[b];
    const int row0 = blockIdx.x * WPB;

    const float zero8[8] = {0.f, 0.f, 0.f, 0.f, 0.f, 0.f, 0.f, 0.f};

    // ---- fast path: whole block is masked rows -> pure zero stream ----
    if (row0 >= L) {
        float* oblk = out + ((size_t)b * TT + (size_t)row0) * TT;
        // 8 rows * 2048 = 16384 floats; 64 per thread as 8 v8 stores
        #pragma unroll
        for (int k = 0; k < 8; k++)
            stcs_v8(oblk + (k * THREADS + tid) * 8, zero8);
        return;
    }

    const int  i         = row0 + warp;            // this warp's row
    const bool row_valid = (i < L);
    float* orow = out + ((size_t)b * TT + (size_t)i) * TT;

    // masked-row warps: zeros have no dependence on staging -> store FIRST
    if (!row_valid) {
        #pragma unroll
        for (int k = 0; k < 8; k++)
            stcs_v8(orow + (k * 32 + lane) * 8, zero8);
    }

    // ---- stage sigmoid(logits[b,:]) into smem (all threads, coalesced) ----
    {
        const float4* src = reinterpret_cast<const float4*>(logits + b * TT);
        #pragma unroll
        for (int k = 0; k < (TT / 4) / THREADS; k++) {
            const float4 x = src[tid + k * THREADS];
            float4 s;
            s.x = __fdividef(1.0f, 1.0f + __expf(-x.x));
            s.y = __fdividef(1.0f, 1.0f + __expf(-x.y));
            s.z = __fdividef(1.0f, 1.0f + __expf(-x.z));
            s.w = __fdividef(1.0f, 1.0f + __expf(-x.w));
            reinterpret_cast<float4*>(s_scores)[tid + k * THREADS] = s;
        }
    }
    __syncthreads();   // the ONLY block barrier

    if (!row_valid) return;

    const float s_i = s_scores[i];
    float e[64];
    float psum = 0.f;

    // chunk k covers j in [k*256, k*256+256); this thread owns the 8
    // CONTIGUOUS j's starting at k*256 + lane*8 (32B-aligned for v8 store).
    #pragma unroll
    for (int k = 0; k < 8; k++) {
        const int j0 = k * 256 + lane * 8;
        if ((k + 1) * 256 <= L) {
            // fully valid chunk: no predication
            const float4 sv0 = reinterpret_cast<const float4*>(s_scores)[j0 / 4];
            const float4 sv1 = reinterpret_cast<const float4*>(s_scores)[j0 / 4 + 1];
            const float sj[8] = {sv0.x, sv0.y, sv0.z, sv0.w,
                                 sv1.x, sv1.y, sv1.z, sv1.w};
            #pragma unroll
            for (int q = 0; q < 8; q++) {
                const float x   = fmaf(-10.0f, fabsf(s_i - sj[q]), 5.0f);
                const float sig = __fdividef(1.0f, 1.0f + __expf(-x));
                const float ev  = __expf(sig);
                e[k * 8 + q] = ev;
                psum += ev;
            }
        } else if (k * 256 >= L) {
            // fully invalid chunk: skip all math
            #pragma unroll
            for (int q = 0; q < 8; q++) e[k * 8 + q] = 0.f;
        } else {
            // straddling chunk (at most one per row): per-element predication
            #pragma unroll
            for (int q = 0; q < 8; q++) {
                const int j = j0 + q;
                float ev = 0.f;
                if (j < L) {
                    const float sj  = s_scores[j];
                    const float x   = fmaf(-10.0f, fabsf(s_i - sj), 5.0f);
                    const float sig = __fdividef(1.0f, 1.0f + __expf(-x));
                    ev = __expf(sig);
                }
                e[k * 8 + q] = ev;
                psum += ev;
            }
        }
    }

    // warp-local butterfly reduction -> every lane has the row sum
    #pragma unroll
    for (int off = 16; off > 0; off >>= 1)
        psum += __shfl_xor_sync(0xFFFFFFFFu, psum, off);
    const float inv = __fdividef(1.0f, psum);

    // normalized 256-bit streaming stores (1KB contiguous per warp-instr)
    #pragma unroll
    for (int k = 0; k < 8; k++) {
        float v[8];
        #pragma unroll
        for (int q = 0; q < 8; q++) v[q] = e[k * 8 + q] * inv;
        stcs_v8(orow + k * 256 + lane * 8, v);
    }
}

extern "C" void kernel_launch(void* const* d_in, const int* in_sizes, int n_in,
                              void* d_out, int out_size) {
    const float* logits  = (const float*)d_in[0];   // [16, 2048, 1] fp32
    const int*   seq_len = (const int*)d_in[1];     // [16] i32
    float*       out     = (float*)d_out;           // [16, 2048, 2048] fp32

    dim3 grid(TT / WPB, BB);
    fused_kernel<<<grid, THREADS>>>(logits, seq_len, out);
}

// round 14
// speedup vs baseline: 1.0530x; 1.0530x over previous
#include <cuda_runtime.h>
#include <cstdint>

// logits [16, 2048, 1] fp32, seq_len [16] i32, out [16, 2048, 2048] fp32.
#define BB 16
#define TT 2048
#define WPB 8                 // warps per block; one output row per warp
#define THREADS (WPB * 32)

// FINAL kernel. Best kernel time of the session (41.92us = 6.40 TB/s
// effective write throughput, 80% of HBM3e spec — the DRAM pure-write wall)
// and best reproducible total (43.456us, measured bit-identically twice).
// The floor was verified invariant across occupancy (32%-87%), barrier
// structure, MUFU load (1x/2x/table), store ordering, eviction policy,
// accumulator shape, and store width (128b vs 256b) over rounds 3-13; no
// SM-side counter ever saturated, so the binding resource is the off-chip
// write path, and the 268 MB poisoned output must be fully written each
// iteration.
//
// Structure: fully-masked blocks stream zeros immediately (no staging);
// masked-row warps in mixed blocks store their zeros before staging;
// valid warps stage sigmoid(logits[b,:]) to smem once (single barrier),
// compute one row each in registers (single MUFU pass), warp-shfl
// reduction, evict-streaming float4 stores.
//
// Max-free softmax is exact: rel values in (0.0067, 0.9933) -> exp in (1, e),
// no overflow; masked entries exactly 0, matching the reference's fp32
// exp(-1e9 - max) == 0.
__global__ __launch_bounds__(THREADS, 3) void fused_kernel(
    const float* __restrict__ logits,
    const int* __restrict__ seq_len,
    float* __restrict__ out)
{
    __shared__ float s_scores[TT];

    const int b    = blockIdx.y;
    const int tid  = threadIdx.x;
    const int warp = tid >> 5;
    const int lane = tid & 31;
    const int L    = seq_len[b];
    const int row0 = blockIdx.x * WPB;

    // ---- fast path: whole block is masked rows -> pure zero stream ----
    if (row0 >= L) {
        const float4 z = make_float4(0.f, 0.f, 0.f, 0.f);
        float* oblk = out + ((size_t)b * TT + (size_t)row0) * TT;
        #pragma unroll
        for (int k = 0; k < 16; k++)
            __stcs(reinterpret_cast<float4*>(oblk) + k * THREADS + tid, z);
        return;
    }

    const int  i         = row0 + warp;            // this warp's row
    const bool row_valid = (i < L);
    float* orow = out + ((size_t)b * TT + (size_t)i) * TT;

    // masked-row warps: zeros have no dependence on staging -> store FIRST,
    // so the store queue is fed while valid warps do MUFU work.
    if (!row_valid) {
        const float4 z = make_float4(0.f, 0.f, 0.f, 0.f);
        #pragma unroll
        for (int k = 0; k < 16; k++)
            __stcs(reinterpret_cast<float4*>(orow) + k * 32 + lane, z);
    }

    // ---- stage sigmoid(logits[b,:]) into smem (all threads, coalesced) ----
    {
        const float4* src = reinterpret_cast<const float4*>(logits + b * TT);
        #pragma unroll
        for (int k = 0; k < (TT / 4) / THREADS; k++) {
            const float4 x = src[tid + k * THREADS];
            float4 s;
            s.x = __fdividef(1.0f, 1.0f + __expf(-x.x));
            s.y = __fdividef(1.0f, 1.0f + __expf(-x.y));
            s.z = __fdividef(1.0f, 1.0f + __expf(-x.z));
            s.w = __fdividef(1.0f, 1.0f + __expf(-x.w));
            reinterpret_cast<float4*>(s_scores)[tid + k * THREADS] = s;
        }
    }
    __syncthreads();   // the ONLY block barrier

    if (!row_valid) return;

    const float s_i = s_scores[i];
    float e[64];
    float psum = 0.f;

    // chunk k covers j in [k*128, k*128+128) across the warp (warp-uniform bounds)
    #pragma unroll
    for (int k = 0; k < 16; k++) {
        const int fidx  = k * 32 + lane;     // float4 index
        const int jbase = fidx * 4;
        if ((k + 1) * 128 <= L) {
            // fully valid chunk: no predication
            const float4 sv = reinterpret_cast<const float4*>(s_scores)[fidx];
            const float sj[4] = {sv.x, sv.y, sv.z, sv.w};
            #pragma unroll
            for (int q = 0; q < 4; q++) {
                const float x   = fmaf(-10.0f, fabsf(s_i - sj[q]), 5.0f);
                const float sig = __fdividef(1.0f, 1.0f + __expf(-x));
                const float ev  = __expf(sig);
                e[k * 4 + q] = ev;
                psum += ev;
            }
        } else if (k * 128 >= L) {
            // fully invalid chunk: skip all math
            #pragma unroll
            for (int q = 0; q < 4; q++) e[k * 4 + q] = 0.f;
        } else {
            // straddling chunk (at most one per row): per-element predication
            #pragma unroll
            for (int q = 0; q < 4; q++) {
                const int j = jbase + q;
                float ev = 0.f;
                if (j < L) {
                    const float sj  = s_scores[j];
                    const float x   = fmaf(-10.0f, fabsf(s_i - sj), 5.0f);
                    const float sig = __fdividef(1.0f, 1.0f + __expf(-x));
                    ev = __expf(sig);
                }
                e[k * 4 + q] = ev;
                psum += ev;
            }
        }
    }

    // warp-local butterfly reduction -> every lane has the row sum
    #pragma unroll
    for (int off = 16; off > 0; off >>= 1)
        psum += __shfl_xor_sync(0xFFFFFFFFu, psum, off);
    const float inv = __fdividef(1.0f, psum);

    // normalized evict-streaming stores (float4, coalesced per chunk)
    #pragma unroll
    for (int k = 0; k < 16; k++) {
        const float4 v = make_float4(e[k * 4 + 0] * inv, e[k * 4 + 1] * inv,
                                     e[k * 4 + 2] * inv, e[k * 4 + 3] * inv);
        __stcs(reinterpret_cast<float4*>(orow) + k * 32 + lane, v);
    }
}

extern "C" void kernel_launch(void* const* d_in, const int* in_sizes, int n_in,
                              void* d_out, int out_size) {
    const float* logits  = (const float*)d_in[0];   // [16, 2048, 1] fp32
    const int*   seq_len = (const int*)d_in[1];     // [16] i32
    float*       out     = (float*)d_out;           // [16, 2048, 2048] fp32

    dim3 grid(TT / WPB, BB);
    fused_kernel<<<grid, THREADS>>>(logits, seq_len, out);
}